// round 1
// baseline (speedup 1.0000x reference)
#include <cuda_runtime.h>
#include <math.h>

#define BB 4
#define SS 2048
#define HH 8
#define DK 64
#define DM 512
#define MTOT (BB*SS)   // 8192
#define SP 68          // smem row stride (floats)

// Scratch (allocation-free rule: __device__ globals)
__device__ float g_Q[BB*HH*SS*DK];
__device__ float g_K[BB*HH*SS*DK];
__device__ float g_V[BB*HH*SS*DK];
__device__ float g_X[BB*SS*DM];

// ---------------------------------------------------------------------------
// GEMM: C[M,N] = A[M,512] @ W[N=512,512]^T + bias.
// Block tile 128(M) x 64(N), BK=16, 256 threads, 8x4 microtile.
// scatter=1: write to [B,H,S,DK] layout (head-split). scatter=0: row-major.
// ---------------------------------------------------------------------------
__global__ __launch_bounds__(256) void gemm_bias_kernel(
    const float* __restrict__ A, const float* __restrict__ W,
    const float* __restrict__ bias, float* __restrict__ out, int scatter)
{
    __shared__ float As[16][132];   // [k][m], m up to 128
    __shared__ float Bs[16][68];    // [k][n]
    const int tid = threadIdx.x;
    const int tx = tid & 15;        // n quad
    const int ty = tid >> 4;        // m oct
    const int m0 = blockIdx.y * 128, n0 = blockIdx.x * 64;

    float acc[8][4];
    #pragma unroll
    for (int i = 0; i < 8; i++)
        #pragma unroll
        for (int j = 0; j < 4; j++) acc[i][j] = 0.f;

    const int ar = tid >> 1;            // 0..127
    const int ak = (tid & 1) * 8;       // 0 or 8
    const int br = tid >> 2;            // 0..63
    const int bk = (tid & 3) * 4;       // 0,4,8,12

    for (int k0 = 0; k0 < DM; k0 += 16) {
        float4 va0 = *(const float4*)(A + (size_t)(m0 + ar) * DM + k0 + ak);
        float4 va1 = *(const float4*)(A + (size_t)(m0 + ar) * DM + k0 + ak + 4);
        float4 vw  = *(const float4*)(W + (size_t)(n0 + br) * DM + k0 + bk);
        As[ak+0][ar] = va0.x; As[ak+1][ar] = va0.y; As[ak+2][ar] = va0.z; As[ak+3][ar] = va0.w;
        As[ak+4][ar] = va1.x; As[ak+5][ar] = va1.y; As[ak+6][ar] = va1.z; As[ak+7][ar] = va1.w;
        Bs[bk+0][br] = vw.x;  Bs[bk+1][br] = vw.y;  Bs[bk+2][br] = vw.z;  Bs[bk+3][br] = vw.w;
        __syncthreads();
        #pragma unroll
        for (int kk = 0; kk < 16; kk++) {
            float4 a0 = *(const float4*)&As[kk][ty*8];
            float4 a1 = *(const float4*)&As[kk][ty*8+4];
            float4 b4 = *(const float4*)&Bs[kk][tx*4];
            float a[8] = {a0.x,a0.y,a0.z,a0.w,a1.x,a1.y,a1.z,a1.w};
            float b[4] = {b4.x,b4.y,b4.z,b4.w};
            #pragma unroll
            for (int i = 0; i < 8; i++)
                #pragma unroll
                for (int j = 0; j < 4; j++)
                    acc[i][j] = fmaf(a[i], b[j], acc[i][j]);
        }
        __syncthreads();
    }

    float4 bvv = *(const float4*)(bias + n0 + tx*4);
    const float bArr[4] = {bvv.x, bvv.y, bvv.z, bvv.w};
    const int h = n0 >> 6;   // head index when scattering (BN==DK==64)
    #pragma unroll
    for (int i = 0; i < 8; i++) {
        int m = m0 + ty*8 + i;
        float4 o4 = make_float4(acc[i][0]+bArr[0], acc[i][1]+bArr[1],
                                acc[i][2]+bArr[2], acc[i][3]+bArr[3]);
        if (scatter) {
            int bb = m / SS, s = m % SS;
            *(float4*)(out + (((size_t)(bb*HH + h)*SS + s)*DK + tx*4)) = o4;
        } else {
            *(float4*)(out + (size_t)m * DM + n0 + tx*4) = o4;
        }
    }
}

// ---------------------------------------------------------------------------
// Flash attention: one CTA per (b, h, 64-query tile). 256 threads.
// Qt/Kt stored d-major [d][r] (conflict-free LDS.128 in QK^T),
// V natural [k][d], P stored transposed [k][r].
// Online softmax: 4 threads per row + shfl reduction.
// ---------------------------------------------------------------------------
__global__ __launch_bounds__(256) void attn_kernel(const int* __restrict__ mask,
                                                   float* __restrict__ X)
{
    extern __shared__ float sm[];
    float* Qt  = sm;                // [64][SP]  Qt[d][r]   (pre-scaled by 1/8)
    float* Kt  = Qt + 64*SP;        // [64][SP]  Kt[d][c]
    float* Vs  = Kt + 64*SP;        // [64][SP]  Vs[k][d]
    float* Pt  = Vs + 64*SP;        // [64][SP]  Pt[k][r]
    float* fac = Pt + 64*SP;        // [64] per-row rescale factor
    float* lrw = fac + 64;          // [64] final row sums

    const int tid = threadIdx.x;
    const int tx = tid & 15, ty = tid >> 4;
    const int q0 = blockIdx.x * 64;
    const int h  = blockIdx.y, b = blockIdx.z;
    const size_t headoff = ((size_t)(b*HH + h)) * SS * DK;

    // Load Q tile transposed + scale by 1/sqrt(64)
    {
        const int rr = tid >> 4, d4 = (tid & 15) * 4;
        #pragma unroll
        for (int p = 0; p < 4; p++) {
            int r = rr + p*16;
            float4 v = *(const float4*)(g_Q + headoff + (size_t)(q0 + r)*DK + d4);
            Qt[(d4+0)*SP + r] = v.x * 0.125f;
            Qt[(d4+1)*SP + r] = v.y * 0.125f;
            Qt[(d4+2)*SP + r] = v.z * 0.125f;
            Qt[(d4+3)*SP + r] = v.w * 0.125f;
        }
    }

    float o[4][4];
    #pragma unroll
    for (int i = 0; i < 4; i++)
        #pragma unroll
        for (int j = 0; j < 4; j++) o[i][j] = 0.f;

    const int sr = tid >> 2;   // softmax row (0..63)
    const int sq = tid & 3;    // quarter of the row
    float m_prev = -INFINITY, lsum = 0.f;

    for (int k0 = 0; k0 < SS; k0 += 64) {
        // Load K (transposed) + V (natural)
        {
            const int rr = tid >> 4, d4 = (tid & 15) * 4;
            #pragma unroll
            for (int p = 0; p < 4; p++) {
                int k = rr + p*16;
                float4 v = *(const float4*)(g_K + headoff + (size_t)(k0 + k)*DK + d4);
                Kt[(d4+0)*SP + k] = v.x;
                Kt[(d4+1)*SP + k] = v.y;
                Kt[(d4+2)*SP + k] = v.z;
                Kt[(d4+3)*SP + k] = v.w;
                float4 w = *(const float4*)(g_V + headoff + (size_t)(k0 + k)*DK + d4);
                *(float4*)(Vs + (size_t)k*SP + d4) = w;
            }
        }
        __syncthreads();

        // S = (Q/8) @ K^T   (4x4 microtile)
        float s[4][4];
        #pragma unroll
        for (int i = 0; i < 4; i++)
            #pragma unroll
            for (int j = 0; j < 4; j++) s[i][j] = 0.f;
        #pragma unroll 16
        for (int d = 0; d < 64; d++) {
            float4 a4 = *(const float4*)(Qt + d*SP + ty*4);
            float4 b4 = *(const float4*)(Kt + d*SP + tx*4);
            float a[4] = {a4.x,a4.y,a4.z,a4.w};
            float bq[4] = {b4.x,b4.y,b4.z,b4.w};
            #pragma unroll
            for (int i = 0; i < 4; i++)
                #pragma unroll
                for (int j = 0; j < 4; j++)
                    s[i][j] = fmaf(a[i], bq[j], s[i][j]);
        }

        // Apply mask, write P transposed: Pt[c][r]
        #pragma unroll
        for (int i = 0; i < 4; i++) {
            int row = q0 + ty*4 + i;
            int4 mm = *(const int4*)(mask + ((size_t)b*SS + row)*SS + k0 + tx*4);
            Pt[(tx*4+0)*SP + ty*4+i] = (mm.x == 0) ? -1e9f : s[i][0];
            Pt[(tx*4+1)*SP + ty*4+i] = (mm.y == 0) ? -1e9f : s[i][1];
            Pt[(tx*4+2)*SP + ty*4+i] = (mm.z == 0) ? -1e9f : s[i][2];
            Pt[(tx*4+3)*SP + ty*4+i] = (mm.w == 0) ? -1e9f : s[i][3];
        }
        __syncthreads();

        // Online softmax over this 64-col block
        {
            float mx = -INFINITY;
            #pragma unroll
            for (int c0 = 0; c0 < 16; c0++)
                mx = fmaxf(mx, Pt[(sq*16 + c0)*SP + sr]);
            mx = fmaxf(mx, __shfl_xor_sync(0xffffffffu, mx, 1));
            mx = fmaxf(mx, __shfl_xor_sync(0xffffffffu, mx, 2));
            float m_new = fmaxf(m_prev, mx);
            float psum = 0.f;
            #pragma unroll
            for (int c0 = 0; c0 < 16; c0++) {
                int c = sq*16 + c0;
                float p = __expf(Pt[c*SP + sr] - m_new);
                Pt[c*SP + sr] = p;
                psum += p;
            }
            psum += __shfl_xor_sync(0xffffffffu, psum, 1);
            psum += __shfl_xor_sync(0xffffffffu, psum, 2);
            float f = __expf(m_prev - m_new);   // exp(-inf)=0 on first block
            lsum = lsum * f + psum;
            m_prev = m_new;
            if (sq == 0) fac[sr] = f;
        }
        __syncthreads();

        // O = O*fac + P @ V
        #pragma unroll
        for (int i = 0; i < 4; i++) {
            float f = fac[ty*4 + i];
            #pragma unroll
            for (int j = 0; j < 4; j++) o[i][j] *= f;
        }
        #pragma unroll 16
        for (int k = 0; k < 64; k++) {
            float4 a4 = *(const float4*)(Pt + k*SP + ty*4);
            float4 b4 = *(const float4*)(Vs + k*SP + tx*4);
            float a[4] = {a4.x,a4.y,a4.z,a4.w};
            float v4[4] = {b4.x,b4.y,b4.z,b4.w};
            #pragma unroll
            for (int i = 0; i < 4; i++)
                #pragma unroll
                for (int j = 0; j < 4; j++)
                    o[i][j] = fmaf(a[i], v4[j], o[i][j]);
        }
        __syncthreads();
    }

    if (sq == 0) lrw[sr] = lsum;
    __syncthreads();

    // Normalize and write to X in [B,S,D_MODEL] layout (ready for Wo GEMM)
    #pragma unroll
    for (int i = 0; i < 4; i++) {
        float inv = 1.0f / lrw[ty*4 + i];
        float4 o4 = make_float4(o[i][0]*inv, o[i][1]*inv, o[i][2]*inv, o[i][3]*inv);
        *(float4*)(X + ((size_t)b*SS + q0 + ty*4 + i)*DM + h*DK + tx*4) = o4;
    }
}

// ---------------------------------------------------------------------------
extern "C" void kernel_launch(void* const* d_in, const int* in_sizes, int n_in,
                              void* d_out, int out_size)
{
    const float* query = (const float*)d_in[0];
    const float* key   = (const float*)d_in[1];
    const float* value = (const float*)d_in[2];
    const int*   mask  = (const int*)  d_in[3];
    const float* Wq = (const float*)d_in[4];
    const float* bq = (const float*)d_in[5];
    const float* Wk = (const float*)d_in[6];
    const float* bk = (const float*)d_in[7];
    const float* Wv = (const float*)d_in[8];
    const float* bv = (const float*)d_in[9];
    const float* Wo = (const float*)d_in[10];
    const float* bo = (const float*)d_in[11];
    float* out = (float*)d_out;

    void *qp, *kp, *vp, *xp;
    cudaGetSymbolAddress(&qp, g_Q);
    cudaGetSymbolAddress(&kp, g_K);
    cudaGetSymbolAddress(&vp, g_V);
    cudaGetSymbolAddress(&xp, g_X);

    dim3 gg(DM/64, MTOT/128);   // (8, 64)
    gemm_bias_kernel<<<gg, 256>>>(query, Wq, bq, (float*)qp, 1);
    gemm_bias_kernel<<<gg, 256>>>(key,   Wk, bk, (float*)kp, 1);
    gemm_bias_kernel<<<gg, 256>>>(value, Wv, bv, (float*)vp, 1);

    const int smem = (4*64*SP + 128) * (int)sizeof(float);   // ~70 KB
    cudaFuncSetAttribute(attn_kernel, cudaFuncAttributeMaxDynamicSharedMemorySize, smem);
    dim3 ag(SS/64, HH, BB);     // (32, 8, 4)
    attn_kernel<<<ag, 256, smem>>>(mask, (float*)xp);

    gemm_bias_kernel<<<gg, 256>>>((const float*)xp, Wo, bo, out, 0);
}

// round 8
// speedup vs baseline: 1.7371x; 1.7371x over previous
#include <cuda_runtime.h>
#include <math.h>

#define BB 4
#define SS 2048
#define HH 8
#define DK 64
#define DM 512
#define MTOT (BB*SS)   // 8192

// Scratch (allocation-free rule: __device__ globals)
__device__ float g_Q[BB*HH*SS*DK];
__device__ float g_K[BB*HH*SS*DK];
__device__ float g_V[BB*HH*SS*DK];
__device__ float g_X[BB*SS*DM];

// ---------------------------------------------------------------------------
// tf32 helpers (mma.sync.m16n8k8, A row-major, B col-major)
// Fragment layout (lane = g*4+tg, g=lane>>2, tg=lane&3):
//   A: a0=(g,tg) a1=(g+8,tg) a2=(g,tg+4) a3=(g+8,tg+4)    [16x8]
//   B: b0=(k=tg,n=g) b1=(k=tg+4,n=g)                      [8x8]
//   C: c0=(g,2tg) c1=(g,2tg+1) c2=(g+8,2tg) c3=(g+8,2tg+1)[16x8]
// ---------------------------------------------------------------------------
__device__ __forceinline__ unsigned f2tf(float f) {
    unsigned u; asm("cvt.rna.tf32.f32 %0, %1;" : "=r"(u) : "f"(f)); return u;
}
__device__ __forceinline__ void mma8(float* d, const unsigned* a, const unsigned* b) {
    asm volatile("mma.sync.aligned.m16n8k8.row.col.f32.tf32.tf32.f32 "
        "{%0,%1,%2,%3},{%4,%5,%6,%7},{%8,%9},{%0,%1,%2,%3};"
        : "+f"(d[0]), "+f"(d[1]), "+f"(d[2]), "+f"(d[3])
        : "r"(a[0]), "r"(a[1]), "r"(a[2]), "r"(a[3]), "r"(b[0]), "r"(b[1]));
}

// ---------------------------------------------------------------------------
// GEMM: C[M,N] = A[M,512] @ W[N,512]^T + bias, tf32 tensor cores.
// Block 128(M)x64(N), 256 threads (8 warps), warp tile 32x32 (2 m-tiles, 4 n-tiles).
// scatter=1: write to [B,H,S,DK] layout. scatter=0: row-major [M,512].
// ---------------------------------------------------------------------------
#define PA 36
__global__ __launch_bounds__(256) void gemm_tf32(
    const float* __restrict__ A, const float* __restrict__ W,
    const float* __restrict__ bias, float* __restrict__ out, int scatter)
{
    __shared__ unsigned As[128*PA];   // [m][k], k<32, pad 36 -> (4g+tg) conflict-free
    __shared__ unsigned Bs[64*PA];    // [n][k]

    const int tid = threadIdx.x, lane = tid & 31, wid = tid >> 5;
    const int g = lane >> 2, tg = lane & 3;
    const int wm = (wid & 3) * 32, wn = (wid >> 2) * 32;
    const int m0 = blockIdx.y * 128, n0 = blockIdx.x * 64;

    float acc[2][4][4];
    #pragma unroll
    for (int mt = 0; mt < 2; mt++)
        #pragma unroll
        for (int nt = 0; nt < 4; nt++)
            #pragma unroll
            for (int i = 0; i < 4; i++) acc[mt][nt][i] = 0.f;

    const int ar = tid >> 1, akb = (tid & 1) * 16;   // A: 128 rows x 32 cols
    const int br = tid >> 2, bkb = (tid & 3) * 8;    // B: 64 rows x 32 cols

    for (int k0 = 0; k0 < DM; k0 += 32) {
        const float* Ap = A + (size_t)(m0 + ar) * DM + k0 + akb;
        #pragma unroll
        for (int i = 0; i < 4; i++) {
            float4 v = *(const float4*)(Ap + i*4);
            *(uint4*)&As[ar*PA + akb + i*4] =
                make_uint4(f2tf(v.x), f2tf(v.y), f2tf(v.z), f2tf(v.w));
        }
        const float* Wp = W + (size_t)(n0 + br) * DM + k0 + bkb;
        #pragma unroll
        for (int i = 0; i < 2; i++) {
            float4 v = *(const float4*)(Wp + i*4);
            *(uint4*)&Bs[br*PA + bkb + i*4] =
                make_uint4(f2tf(v.x), f2tf(v.y), f2tf(v.z), f2tf(v.w));
        }
        __syncthreads();

        #pragma unroll
        for (int kk = 0; kk < 32; kk += 8) {
            unsigned a[2][4], b[4][2];
            #pragma unroll
            for (int mt = 0; mt < 2; mt++) {
                int mr = wm + mt*16 + g;
                a[mt][0] = As[mr*PA + kk + tg];
                a[mt][1] = As[(mr+8)*PA + kk + tg];
                a[mt][2] = As[mr*PA + kk + tg + 4];
                a[mt][3] = As[(mr+8)*PA + kk + tg + 4];
            }
            #pragma unroll
            for (int nt = 0; nt < 4; nt++) {
                int nr = wn + nt*8 + g;
                b[nt][0] = Bs[nr*PA + kk + tg];
                b[nt][1] = Bs[nr*PA + kk + tg + 4];
            }
            #pragma unroll
            for (int mt = 0; mt < 2; mt++)
                #pragma unroll
                for (int nt = 0; nt < 4; nt++)
                    mma8(acc[mt][nt], a[mt], b[nt]);
        }
        __syncthreads();
    }

    #pragma unroll
    for (int mt = 0; mt < 2; mt++) {
        int r0 = m0 + wm + mt*16 + g;
        int r1 = r0 + 8;
        #pragma unroll
        for (int nt = 0; nt < 4; nt++) {
            int c = n0 + wn + nt*8 + tg*2;
            float2 bv = *(const float2*)(bias + c);
            float2 v0 = make_float2(acc[mt][nt][0] + bv.x, acc[mt][nt][1] + bv.y);
            float2 v1 = make_float2(acc[mt][nt][2] + bv.x, acc[mt][nt][3] + bv.y);
            if (scatter) {
                int hh = c >> 6, dd = c & 63;
                int b0 = r0 >> 11, s0 = r0 & (SS-1);
                int b1 = r1 >> 11, s1 = r1 & (SS-1);
                *(float2*)(out + (((size_t)(b0*HH + hh))*SS + s0)*DK + dd) = v0;
                *(float2*)(out + (((size_t)(b1*HH + hh))*SS + s1)*DK + dd) = v1;
            } else {
                *(float2*)(out + (size_t)r0 * DM + c) = v0;
                *(float2*)(out + (size_t)r1 * DM + c) = v1;
            }
        }
    }
}

// ---------------------------------------------------------------------------
// Flash attention, tf32 tensor cores. One CTA per (b, h, 64-query tile).
// 256 threads = 8 warps; warp layout 4(q) x 2(k/d); warp tile 16 x 32.
// QK^T and PV via mma.sync; fp32 online softmax (4 threads/row + shfl).
// ---------------------------------------------------------------------------
#define QP 68
#define VP 72
__global__ __launch_bounds__(256) void attn_tf32(const int* __restrict__ mask,
                                                 float* __restrict__ X)
{
    extern __shared__ unsigned smb[];
    unsigned* Qs = smb;               // [64][QP] tf32, pre-scaled 1/8
    unsigned* Ks = Qs + 64*QP;        // [64][QP] tf32
    unsigned* Vs = Ks + 64*QP;        // [64][VP] tf32 (pad 72: (8tg+g) conflict-free)
    float* Sm  = (float*)(Vs + 64*VP);// [64][QP] fp32 scores / probs
    float* fac = Sm + 64*QP;          // [64]
    float* lrw = fac + 64;            // [64]

    const int tid = threadIdx.x, lane = tid & 31, wid = tid >> 5;
    const int g = lane >> 2, tg = lane & 3;
    const int wq = (wid & 3) * 16, wk = (wid >> 2) * 32;
    const int q0 = blockIdx.x * 64, h = blockIdx.y, b = blockIdx.z;
    const size_t hoff = ((size_t)(b*HH + h)) * SS * DK;

    // Load Q tile (scaled by 1/sqrt(64))
    {
        int r = tid >> 2, cb = (tid & 3) * 16;
        const float* src = g_Q + hoff + (size_t)(q0 + r)*DK + cb;
        #pragma unroll
        for (int i = 0; i < 4; i++) {
            float4 v = *(const float4*)(src + i*4);
            *(uint4*)&Qs[r*QP + cb + i*4] = make_uint4(
                f2tf(v.x*0.125f), f2tf(v.y*0.125f), f2tf(v.z*0.125f), f2tf(v.w*0.125f));
        }
    }

    float o[4][4];
    #pragma unroll
    for (int nt = 0; nt < 4; nt++)
        #pragma unroll
        for (int i = 0; i < 4; i++) o[nt][i] = 0.f;

    const int sr = tid >> 2, sq = tid & 3;
    float m_prev = -INFINITY, lsum = 0.f;

    for (int k0 = 0; k0 < SS; k0 += 64) {
        // Load K, V tiles
        {
            int r = tid >> 2, cb = (tid & 3) * 16;
            const float* ks = g_K + hoff + (size_t)(k0 + r)*DK + cb;
            const float* vs = g_V + hoff + (size_t)(k0 + r)*DK + cb;
            #pragma unroll
            for (int i = 0; i < 4; i++) {
                float4 v = *(const float4*)(ks + i*4);
                *(uint4*)&Ks[r*QP + cb + i*4] =
                    make_uint4(f2tf(v.x), f2tf(v.y), f2tf(v.z), f2tf(v.w));
                float4 w = *(const float4*)(vs + i*4);
                *(uint4*)&Vs[r*VP + cb + i*4] =
                    make_uint4(f2tf(w.x), f2tf(w.y), f2tf(w.z), f2tf(w.w));
            }
        }
        __syncthreads();

        // S = (Q/8) @ K^T  : 16x32 per warp
        float s[4][4];
        #pragma unroll
        for (int nt = 0; nt < 4; nt++)
            #pragma unroll
            for (int i = 0; i < 4; i++) s[nt][i] = 0.f;
        #pragma unroll
        for (int kk = 0; kk < 64; kk += 8) {
            unsigned a[4], bfr[4][2];
            a[0] = Qs[(wq+g)*QP + kk + tg];
            a[1] = Qs[(wq+g+8)*QP + kk + tg];
            a[2] = Qs[(wq+g)*QP + kk + tg + 4];
            a[3] = Qs[(wq+g+8)*QP + kk + tg + 4];
            #pragma unroll
            for (int nt = 0; nt < 4; nt++) {
                bfr[nt][0] = Ks[(wk+nt*8+g)*QP + kk + tg];
                bfr[nt][1] = Ks[(wk+nt*8+g)*QP + kk + tg + 4];
            }
            #pragma unroll
            for (int nt = 0; nt < 4; nt++) mma8(s[nt], a, bfr[nt]);
        }

        // Apply mask, spill S to smem
        {
            const int* mr0 = mask + ((size_t)b*SS + (q0 + wq + g))*SS + k0;
            const int* mr1 = mr0 + 8*SS;
            #pragma unroll
            for (int nt = 0; nt < 4; nt++) {
                int c = wk + nt*8 + tg*2;
                int2 m0v = *(const int2*)(mr0 + c);
                int2 m1v = *(const int2*)(mr1 + c);
                Sm[(wq+g)*QP + c]     = m0v.x ? s[nt][0] : -1e9f;
                Sm[(wq+g)*QP + c+1]   = m0v.y ? s[nt][1] : -1e9f;
                Sm[(wq+g+8)*QP + c]   = m1v.x ? s[nt][2] : -1e9f;
                Sm[(wq+g+8)*QP + c+1] = m1v.y ? s[nt][3] : -1e9f;
            }
        }
        __syncthreads();

        // Online softmax over this 64-col block
        {
            float mx = -INFINITY;
            #pragma unroll
            for (int i = 0; i < 16; i++)
                mx = fmaxf(mx, Sm[sr*QP + sq*16 + i]);
            mx = fmaxf(mx, __shfl_xor_sync(0xffffffffu, mx, 1));
            mx = fmaxf(mx, __shfl_xor_sync(0xffffffffu, mx, 2));
            float m_new = fmaxf(m_prev, mx);
            float ps = 0.f;
            #pragma unroll
            for (int i = 0; i < 16; i++) {
                float p = __expf(Sm[sr*QP + sq*16 + i] - m_new);
                Sm[sr*QP + sq*16 + i] = p;
                ps += p;
            }
            ps += __shfl_xor_sync(0xffffffffu, ps, 1);
            ps += __shfl_xor_sync(0xffffffffu, ps, 2);
            float f = __expf(m_prev - m_new);   // exp(-inf)=0 on first block
            lsum = lsum * f + ps;
            m_prev = m_new;
            if (sq == 0) fac[sr] = f;
        }
        __syncthreads();

        // O = O*fac + P @ V
        {
            float f0 = fac[wq+g], f1 = fac[wq+g+8];
            #pragma unroll
            for (int nt = 0; nt < 4; nt++) {
                o[nt][0] *= f0; o[nt][1] *= f0;
                o[nt][2] *= f1; o[nt][3] *= f1;
            }
            #pragma unroll
            for (int kk = 0; kk < 64; kk += 8) {
                unsigned a[4], bfr[4][2];
                a[0] = f2tf(Sm[(wq+g)*QP + kk + tg]);
                a[1] = f2tf(Sm[(wq+g+8)*QP + kk + tg]);
                a[2] = f2tf(Sm[(wq+g)*QP + kk + tg + 4]);
                a[3] = f2tf(Sm[(wq+g+8)*QP + kk + tg + 4]);
                #pragma unroll
                for (int nt = 0; nt < 4; nt++) {
                    bfr[nt][0] = Vs[(kk+tg)*VP + wk + nt*8 + g];
                    bfr[nt][1] = Vs[(kk+tg+4)*VP + wk + nt*8 + g];
                }
                #pragma unroll
                for (int nt = 0; nt < 4; nt++) mma8(o[nt], a, bfr[nt]);
            }
        }
        __syncthreads();
    }

    if (sq == 0) lrw[sr] = lsum;
    __syncthreads();

    // Normalize, write X in [B,S,DM] layout (head-merged, ready for Wo GEMM)
    {
        float i0 = 1.f / lrw[wq+g], i1 = 1.f / lrw[wq+g+8];
        float* x0 = X + ((size_t)b*SS + q0 + wq + g)*DM + h*DK;
        float* x1 = X + ((size_t)b*SS + q0 + wq + g + 8)*DM + h*DK;
        #pragma unroll
        for (int nt = 0; nt < 4; nt++) {
            int c = wk + nt*8 + tg*2;
            *(float2*)(x0 + c) = make_float2(o[nt][0]*i0, o[nt][1]*i0);
            *(float2*)(x1 + c) = make_float2(o[nt][2]*i1, o[nt][3]*i1);
        }
    }
}

// ---------------------------------------------------------------------------
extern "C" void kernel_launch(void* const* d_in, const int* in_sizes, int n_in,
                              void* d_out, int out_size)
{
    const float* query = (const float*)d_in[0];
    const float* key   = (const float*)d_in[1];
    const float* value = (const float*)d_in[2];
    const int*   mask  = (const int*)  d_in[3];
    const float* Wq = (const float*)d_in[4];
    const float* bq = (const float*)d_in[5];
    const float* Wk = (const float*)d_in[6];
    const float* bk = (const float*)d_in[7];
    const float* Wv = (const float*)d_in[8];
    const float* bv = (const float*)d_in[9];
    const float* Wo = (const float*)d_in[10];
    const float* bo = (const float*)d_in[11];
    float* out = (float*)d_out;

    void *qp, *kp, *vp, *xp;
    cudaGetSymbolAddress(&qp, g_Q);
    cudaGetSymbolAddress(&kp, g_K);
    cudaGetSymbolAddress(&vp, g_V);
    cudaGetSymbolAddress(&xp, g_X);

    dim3 gg(DM/64, MTOT/128);   // (8, 64)
    gemm_tf32<<<gg, 256>>>(query, Wq, bq, (float*)qp, 1);
    gemm_tf32<<<gg, 256>>>(key,   Wk, bk, (float*)kp, 1);
    gemm_tf32<<<gg, 256>>>(value, Wv, bv, (float*)vp, 1);

    const int smem = (64*QP*3 + 64*VP + 128) * (int)sizeof(float);  // ~71 KB
    cudaFuncSetAttribute(attn_tf32, cudaFuncAttributeMaxDynamicSharedMemorySize, smem);
    dim3 ag(SS/64, HH, BB);     // (32, 8, 4)
    attn_tf32<<<ag, 256, smem>>>(mask, (float*)xp);

    gemm_tf32<<<gg, 256>>>((const float*)xp, Wo, bo, out, 0);
}

// round 9
// speedup vs baseline: 2.1695x; 1.2489x over previous
#include <cuda_runtime.h>
#include <math.h>

#define BB 4
#define SS 2048
#define HH 8
#define DK 64
#define DM 512
#define MTOT (BB*SS)   // 8192

// Scratch (allocation-free rule: __device__ globals)
__device__ float g_Q[BB*HH*SS*DK];
__device__ float g_K[BB*HH*SS*DK];
__device__ float g_V[BB*HH*SS*DK];
__device__ float g_X[BB*SS*DM];

// ---------------------------------------------------------------------------
// tf32 mma.sync.m16n8k8 (A row-major, B col-major). Lane = g*4+tg.
//   A: a0=(g,tg) a1=(g+8,tg) a2=(g,tg+4) a3=(g+8,tg+4)
//   B: b0=(k=tg,n=g) b1=(k=tg+4,n=g)
//   C: c0=(g,2tg) c1=(g,2tg+1) c2=(g+8,2tg) c3=(g+8,2tg+1)
// HMMA.tf32 ignores the low 13 mantissa bits -> raw fp32 bit patterns are
// valid tf32 operands (truncation instead of rna; ~0.5 ulp extra error).
// ---------------------------------------------------------------------------
__device__ __forceinline__ unsigned f2tf(float f) {
    unsigned u; asm("cvt.rna.tf32.f32 %0, %1;" : "=r"(u) : "f"(f)); return u;
}
__device__ __forceinline__ void mma8(float* d, const unsigned* a, const unsigned* b) {
    asm volatile("mma.sync.aligned.m16n8k8.row.col.f32.tf32.tf32.f32 "
        "{%0,%1,%2,%3},{%4,%5,%6,%7},{%8,%9},{%0,%1,%2,%3};"
        : "+f"(d[0]), "+f"(d[1]), "+f"(d[2]), "+f"(d[3])
        : "r"(a[0]), "r"(a[1]), "r"(a[2]), "r"(a[3]), "r"(b[0]), "r"(b[1]));
}
__device__ __forceinline__ void cp16(void* smem, const void* g) {
    unsigned saddr = (unsigned)__cvta_generic_to_shared(smem);
    asm volatile("cp.async.cg.shared.global [%0], [%1], 16;"
                 :: "r"(saddr), "l"(g) : "memory");
}

// ---------------------------------------------------------------------------
// GEMM: C[M,N] = A[M,512] @ W[N,512]^T + bias, tf32 tensor cores.
// Block 128(M)x64(N), 256 threads, warp tile 32x32. Register-prefetch pipeline.
// scatter=1: write to [B,H,S,DK] layout. scatter=0: row-major [M,512].
// ---------------------------------------------------------------------------
#define PA 36
__global__ __launch_bounds__(256) void gemm_tf32(
    const float* __restrict__ A, const float* __restrict__ W,
    const float* __restrict__ bias, float* __restrict__ out, int scatter)
{
    __shared__ unsigned As[128*PA];
    __shared__ unsigned Bs[64*PA];

    const int tid = threadIdx.x, lane = tid & 31, wid = tid >> 5;
    const int g = lane >> 2, tg = lane & 3;
    const int wm = (wid & 3) * 32, wn = (wid >> 2) * 32;
    const int m0 = blockIdx.y * 128, n0 = blockIdx.x * 64;

    float acc[2][4][4];
    #pragma unroll
    for (int mt = 0; mt < 2; mt++)
        #pragma unroll
        for (int nt = 0; nt < 4; nt++)
            #pragma unroll
            for (int i = 0; i < 4; i++) acc[mt][nt][i] = 0.f;

    const int ar = tid >> 1, akb = (tid & 1) * 16;
    const int br = tid >> 2, bkb = (tid & 3) * 8;
    const float* Abase = A + (size_t)(m0 + ar) * DM + akb;
    const float* Wbase = W + (size_t)(n0 + br) * DM + bkb;

    float4 pva[4], pvw[2];
    #pragma unroll
    for (int i = 0; i < 4; i++) pva[i] = *(const float4*)(Abase + i*4);
    #pragma unroll
    for (int i = 0; i < 2; i++) pvw[i] = *(const float4*)(Wbase + i*4);

    for (int k0 = 0; k0 < DM; k0 += 32) {
        #pragma unroll
        for (int i = 0; i < 4; i++) {
            float4 v = pva[i];
            *(uint4*)&As[ar*PA + akb + i*4] =
                make_uint4(f2tf(v.x), f2tf(v.y), f2tf(v.z), f2tf(v.w));
        }
        #pragma unroll
        for (int i = 0; i < 2; i++) {
            float4 v = pvw[i];
            *(uint4*)&Bs[br*PA + bkb + i*4] =
                make_uint4(f2tf(v.x), f2tf(v.y), f2tf(v.z), f2tf(v.w));
        }
        __syncthreads();

        if (k0 + 32 < DM) {     // prefetch next k-slab (overlaps MMA below)
            #pragma unroll
            for (int i = 0; i < 4; i++) pva[i] = *(const float4*)(Abase + k0+32 + i*4);
            #pragma unroll
            for (int i = 0; i < 2; i++) pvw[i] = *(const float4*)(Wbase + k0+32 + i*4);
        }

        #pragma unroll
        for (int kk = 0; kk < 32; kk += 8) {
            unsigned a[2][4], b[4][2];
            #pragma unroll
            for (int mt = 0; mt < 2; mt++) {
                int mr = wm + mt*16 + g;
                a[mt][0] = As[mr*PA + kk + tg];
                a[mt][1] = As[(mr+8)*PA + kk + tg];
                a[mt][2] = As[mr*PA + kk + tg + 4];
                a[mt][3] = As[(mr+8)*PA + kk + tg + 4];
            }
            #pragma unroll
            for (int nt = 0; nt < 4; nt++) {
                int nr = wn + nt*8 + g;
                b[nt][0] = Bs[nr*PA + kk + tg];
                b[nt][1] = Bs[nr*PA + kk + tg + 4];
            }
            #pragma unroll
            for (int mt = 0; mt < 2; mt++)
                #pragma unroll
                for (int nt = 0; nt < 4; nt++)
                    mma8(acc[mt][nt], a[mt], b[nt]);
        }
        __syncthreads();
    }

    #pragma unroll
    for (int mt = 0; mt < 2; mt++) {
        int r0 = m0 + wm + mt*16 + g;
        int r1 = r0 + 8;
        #pragma unroll
        for (int nt = 0; nt < 4; nt++) {
            int c = n0 + wn + nt*8 + tg*2;
            float2 bv = *(const float2*)(bias + c);
            float2 v0 = make_float2(acc[mt][nt][0] + bv.x, acc[mt][nt][1] + bv.y);
            float2 v1 = make_float2(acc[mt][nt][2] + bv.x, acc[mt][nt][3] + bv.y);
            if (scatter) {
                int hh = c >> 6, dd = c & 63;
                int b0 = r0 >> 11, s0 = r0 & (SS-1);
                int b1 = r1 >> 11, s1 = r1 & (SS-1);
                *(float2*)(out + (((size_t)(b0*HH + hh))*SS + s0)*DK + dd) = v0;
                *(float2*)(out + (((size_t)(b1*HH + hh))*SS + s1)*DK + dd) = v1;
            } else {
                *(float2*)(out + (size_t)r0 * DM + c) = v0;
                *(float2*)(out + (size_t)r1 * DM + c) = v1;
            }
        }
    }
}

// ---------------------------------------------------------------------------
// Flash attention, tf32. One CTA per (b, h, 128-query tile). 256 thr = 8 warps,
// warp grid 4(q) x 2(k or d), warp tile 32x32. Register-resident softmax:
// S never spilled; only exp'd P goes to smem (once) for the PV A-fragments.
// K/V loaded via cp.async (raw fp32 bits == valid tf32 operands).
// ---------------------------------------------------------------------------
#define QT 128
#define KT 64
#define QSP 68   // stride (words) for Qs/Ks/Pm: frag loads land on 32 distinct banks
#define VSP 72   // stride for Vs: PV B-frag scalar loads conflict-free
__global__ __launch_bounds__(256, 2) void attn_tf32(const int* __restrict__ mask,
                                                    float* __restrict__ X)
{
    extern __shared__ float smf[];
    float* Qs   = smf;                   // [128][QSP] fp32 bits (Q/8)
    float* Ks   = Qs + 128*QSP;          // [64][QSP]
    float* Vs   = Ks + 64*QSP;           // [64][VSP]
    float* Pm   = Vs + 64*VSP;           // [128][QSP] exp'd probs
    float* pmax = Pm + 128*QSP;          // [2][128]
    float* psum = pmax + 256;            // [2][128]

    const int tid = threadIdx.x, lane = tid & 31, wid = tid >> 5;
    const int g = lane >> 2, tg = lane & 3;
    const int wq = (wid & 3) * 32, wk = (wid >> 2) * 32;
    const int wki = wid >> 2;
    const int q0 = blockIdx.x * QT, h = blockIdx.y, b = blockIdx.z;
    const size_t hoff = ((size_t)(b*HH + h)) * SS * DK;

    // Load Q tile (scaled by 1/sqrt(64); raw fp32 bits used as tf32)
    {
        int r = tid >> 1, cb = (tid & 1) * 32;
        const float* src = g_Q + hoff + (size_t)(q0 + r)*DK + cb;
        #pragma unroll
        for (int j = 0; j < 8; j++) {
            float4 v = *(const float4*)(src + j*4);
            *(float4*)&Qs[r*QSP + cb + j*4] =
                make_float4(v.x*0.125f, v.y*0.125f, v.z*0.125f, v.w*0.125f);
        }
    }

    float o[2][4][4];
    #pragma unroll
    for (int mt = 0; mt < 2; mt++)
        #pragma unroll
        for (int nt = 0; nt < 4; nt++)
            #pragma unroll
            for (int i = 0; i < 4; i++) o[mt][nt][i] = 0.f;

    float mprev[2][2], lsum[2][2];
    #pragma unroll
    for (int mt = 0; mt < 2; mt++)
        #pragma unroll
        for (int h2 = 0; h2 < 2; h2++) { mprev[mt][h2] = -INFINITY; lsum[mt][h2] = 0.f; }

    const int kr = tid & 63, kdg = (tid >> 6) * 16;   // K/V loader mapping

    for (int k0 = 0; k0 < SS; k0 += KT) {
        __syncthreads();   // Ks/Vs (and Qs on iter 0) safe to (over)write / read done
        {
            const float* kp = g_K + hoff + (size_t)(k0 + kr)*DK + kdg;
            const float* vp = g_V + hoff + (size_t)(k0 + kr)*DK + kdg;
            #pragma unroll
            for (int j = 0; j < 4; j++) {
                cp16(&Ks[kr*QSP + kdg + j*4], kp + j*4);
                cp16(&Vs[kr*VSP + kdg + j*4], vp + j*4);
            }
            asm volatile("cp.async.commit_group;\ncp.async.wait_group 0;" ::: "memory");
        }
        __syncthreads();

        // ---- S = (Q/8) @ K^T : 32x64 per warp-row covered by warp pair ----
        float s[2][4][4];
        #pragma unroll
        for (int mt = 0; mt < 2; mt++)
            #pragma unroll
            for (int nt = 0; nt < 4; nt++)
                #pragma unroll
                for (int i = 0; i < 4; i++) s[mt][nt][i] = 0.f;

        #pragma unroll
        for (int kk = 0; kk < 64; kk += 8) {
            unsigned a[2][4], bb[4][2];
            #pragma unroll
            for (int mt = 0; mt < 2; mt++) {
                int r = wq + mt*16 + g;
                a[mt][0] = __float_as_uint(Qs[r*QSP + kk + tg]);
                a[mt][1] = __float_as_uint(Qs[(r+8)*QSP + kk + tg]);
                a[mt][2] = __float_as_uint(Qs[r*QSP + kk + tg + 4]);
                a[mt][3] = __float_as_uint(Qs[(r+8)*QSP + kk + tg + 4]);
            }
            #pragma unroll
            for (int nt = 0; nt < 4; nt++) {
                int c = wk + nt*8 + g;
                bb[nt][0] = __float_as_uint(Ks[c*QSP + kk + tg]);
                bb[nt][1] = __float_as_uint(Ks[c*QSP + kk + tg + 4]);
            }
            #pragma unroll
            for (int mt = 0; mt < 2; mt++)
                #pragma unroll
                for (int nt = 0; nt < 4; nt++)
                    mma8(s[mt][nt], a[mt], bb[nt]);
        }

        // ---- mask (register-resident) ----
        #pragma unroll
        for (int mt = 0; mt < 2; mt++)
            #pragma unroll
            for (int h2 = 0; h2 < 2; h2++) {
                int row = q0 + wq + mt*16 + h2*8 + g;
                const int* mp = mask + ((size_t)b*SS + row)*SS + k0 + wk;
                #pragma unroll
                for (int nt = 0; nt < 4; nt++) {
                    int2 mm = *(const int2*)(mp + nt*8 + tg*2);
                    if (mm.x == 0) s[mt][nt][h2*2]   = -1e9f;
                    if (mm.y == 0) s[mt][nt][h2*2+1] = -1e9f;
                }
            }

        // ---- per-row max (in-register + shfl + cross-warp exchange) ----
        #pragma unroll
        for (int mt = 0; mt < 2; mt++)
            #pragma unroll
            for (int h2 = 0; h2 < 2; h2++) {
                float m = fmaxf(s[mt][0][h2*2], s[mt][0][h2*2+1]);
                #pragma unroll
                for (int nt = 1; nt < 4; nt++)
                    m = fmaxf(m, fmaxf(s[mt][nt][h2*2], s[mt][nt][h2*2+1]));
                m = fmaxf(m, __shfl_xor_sync(0xffffffffu, m, 1));
                m = fmaxf(m, __shfl_xor_sync(0xffffffffu, m, 2));
                if (tg == 0) pmax[wki*128 + wq + mt*16 + h2*8 + g] = m;
            }
        __syncthreads();

        // ---- combine max, exp in registers, partial sums, spill P ----
        float fr[2][2];
        #pragma unroll
        for (int mt = 0; mt < 2; mt++)
            #pragma unroll
            for (int h2 = 0; h2 < 2; h2++) {
                int row = wq + mt*16 + h2*8 + g;
                float mn = fmaxf(pmax[row], pmax[128 + row]);
                mn = fmaxf(mprev[mt][h2], mn);
                fr[mt][h2] = __expf(mprev[mt][h2] - mn);   // exp(-inf)=0 first iter
                mprev[mt][h2] = mn;
                float ssum = 0.f;
                #pragma unroll
                for (int nt = 0; nt < 4; nt++) {
                    float p0 = __expf(s[mt][nt][h2*2]   - mn);
                    float p1 = __expf(s[mt][nt][h2*2+1] - mn);
                    s[mt][nt][h2*2] = p0; s[mt][nt][h2*2+1] = p1;
                    ssum += p0 + p1;
                }
                ssum += __shfl_xor_sync(0xffffffffu, ssum, 1);
                ssum += __shfl_xor_sync(0xffffffffu, ssum, 2);
                if (tg == 0) psum[wki*128 + row] = ssum;
            }
        #pragma unroll
        for (int mt = 0; mt < 2; mt++)
            #pragma unroll
            for (int h2 = 0; h2 < 2; h2++) {
                int r = wq + mt*16 + h2*8 + g;
                #pragma unroll
                for (int nt = 0; nt < 4; nt++)
                    *(float2*)&Pm[r*QSP + wk + nt*8 + tg*2] =
                        make_float2(s[mt][nt][h2*2], s[mt][nt][h2*2+1]);
            }
        __syncthreads();

        // ---- update l, rescale O, O += P @ V ----
        #pragma unroll
        for (int mt = 0; mt < 2; mt++)
            #pragma unroll
            for (int h2 = 0; h2 < 2; h2++) {
                int row = wq + mt*16 + h2*8 + g;
                lsum[mt][h2] = lsum[mt][h2]*fr[mt][h2] + psum[row] + psum[128 + row];
            }
        #pragma unroll
        for (int mt = 0; mt < 2; mt++)
            #pragma unroll
            for (int nt = 0; nt < 4; nt++) {
                o[mt][nt][0] *= fr[mt][0]; o[mt][nt][1] *= fr[mt][0];
                o[mt][nt][2] *= fr[mt][1]; o[mt][nt][3] *= fr[mt][1];
            }
        #pragma unroll
        for (int kk = 0; kk < 64; kk += 8) {
            unsigned a[2][4], bb[4][2];
            #pragma unroll
            for (int mt = 0; mt < 2; mt++) {
                int r = wq + mt*16 + g;
                a[mt][0] = __float_as_uint(Pm[r*QSP + kk + tg]);
                a[mt][1] = __float_as_uint(Pm[(r+8)*QSP + kk + tg]);
                a[mt][2] = __float_as_uint(Pm[r*QSP + kk + tg + 4]);
                a[mt][3] = __float_as_uint(Pm[(r+8)*QSP + kk + tg + 4]);
            }
            #pragma unroll
            for (int nt = 0; nt < 4; nt++) {
                int c = wk + nt*8 + g;   // d-column for this warp
                bb[nt][0] = __float_as_uint(Vs[(kk+tg)*VSP + c]);
                bb[nt][1] = __float_as_uint(Vs[(kk+tg+4)*VSP + c]);
            }
            #pragma unroll
            for (int mt = 0; mt < 2; mt++)
                #pragma unroll
                for (int nt = 0; nt < 4; nt++)
                    mma8(o[mt][nt], a[mt], bb[nt]);
        }
    }

    // ---- normalize, write X in [B,S,DM] (head-merged for Wo GEMM) ----
    #pragma unroll
    for (int mt = 0; mt < 2; mt++)
        #pragma unroll
        for (int h2 = 0; h2 < 2; h2++) {
            int r = q0 + wq + mt*16 + h2*8 + g;
            float inv = 1.f / lsum[mt][h2];
            float* xp = X + ((size_t)b*SS + r)*DM + h*DK + wk;
            #pragma unroll
            for (int nt = 0; nt < 4; nt++)
                *(float2*)(xp + nt*8 + tg*2) =
                    make_float2(o[mt][nt][h2*2]*inv, o[mt][nt][h2*2+1]*inv);
        }
}

// ---------------------------------------------------------------------------
extern "C" void kernel_launch(void* const* d_in, const int* in_sizes, int n_in,
                              void* d_out, int out_size)
{
    const float* query = (const float*)d_in[0];
    const float* key   = (const float*)d_in[1];
    const float* value = (const float*)d_in[2];
    const int*   mask  = (const int*)  d_in[3];
    const float* Wq = (const float*)d_in[4];
    const float* bq = (const float*)d_in[5];
    const float* Wk = (const float*)d_in[6];
    const float* bk = (const float*)d_in[7];
    const float* Wv = (const float*)d_in[8];
    const float* bv = (const float*)d_in[9];
    const float* Wo = (const float*)d_in[10];
    const float* bo = (const float*)d_in[11];
    float* out = (float*)d_out;

    void *qp, *kp, *vp, *xp;
    cudaGetSymbolAddress(&qp, g_Q);
    cudaGetSymbolAddress(&kp, g_K);
    cudaGetSymbolAddress(&vp, g_V);
    cudaGetSymbolAddress(&xp, g_X);

    dim3 gg(DM/64, MTOT/128);   // (8, 64)
    gemm_tf32<<<gg, 256>>>(query, Wq, bq, (float*)qp, 1);
    gemm_tf32<<<gg, 256>>>(key,   Wk, bk, (float*)kp, 1);
    gemm_tf32<<<gg, 256>>>(value, Wv, bv, (float*)vp, 1);

    const int smem = (128*QSP + 64*QSP + 64*VSP + 128*QSP + 512) * (int)sizeof(float);
    cudaFuncSetAttribute(attn_tf32, cudaFuncAttributeMaxDynamicSharedMemorySize, smem);
    dim3 ag(SS/QT, HH, BB);     // (16, 8, 4)
    attn_tf32<<<ag, 256, smem>>>(mask, (float*)xp);

    gemm_tf32<<<gg, 256>>>((const float*)xp, Wo, bo, out, 0);
}